// round 2
// baseline (speedup 1.0000x reference)
#include <cuda_runtime.h>

#define B_   2
#define C_   32
#define T_   64
#define HW_  4096
#define N_   512
#define CH_  16
#define FT_  400
#define L_   (FT_*N_)        /* 204800 */
#define CNT_ (B_*L_)         /* 409600 */
#define OUT_OFF_RESULT ((size_t)B_*CH_*L_)  /* 6,553,600 */

// ---- scratch (device globals) ----
__device__ float g_Weff[CH_*C_];                         // transposed: [c][o]
__device__ float g_beff[CH_];
__device__ __align__(16) float g_r[B_*T_*HW_];           // 2 MB
__device__ __align__(16) float g_f[(size_t)B_*N_*T_*CH_]; // 4 MB, layout [bn][t][o]
__device__ float g_part[1024*32];
__device__ float g_scale[CH_];
__device__ float g_shift[CH_];

// Fold W1@Wf -> Weff (stored transposed [c][o]), b1 + W1@bf -> beff
__global__ void k_init(const float* __restrict__ W1, const float* __restrict__ Wf,
                       const float* __restrict__ b1, const float* __restrict__ bf) {
    int t = threadIdx.x;                 // 512 threads
    int o = t >> 5, c = t & 31;
    float a = 0.f;
    #pragma unroll
    for (int k = 0; k < 32; k++) a += W1[o*32+k] * Wf[k*32+c];
    g_Weff[c*CH_ + o] = a;               // transposed store
    if (t < CH_) {
        float bb = b1[t];
        #pragma unroll
        for (int k = 0; k < 32; k++) bb += W1[t*32+k] * bf[k];
        g_beff[t] = bb;
    }
}

// r[b][t][hw] = Wr . x[b][:][t][hw] + br  — float4, streams x (67 MB)
__global__ void k_r(const float* __restrict__ x, const float* __restrict__ Wr,
                    const float* __restrict__ br) {
    __shared__ float w[32];
    if (threadIdx.x < 32) w[threadIdx.x] = Wr[threadIdx.x];
    __syncthreads();
    int tid = blockIdx.x*blockDim.x + threadIdx.x;   // 131072 (each does 4 hw)
    int hw4 = tid & 1023;
    int bt  = tid >> 10;
    int b = bt >> 6, t = bt & 63;
    const float4* xp = (const float4*)(x + (size_t)(b*C_*T_ + t)*HW_) + hw4;
    float4 acc; float brv = br[0];
    acc.x = brv; acc.y = brv; acc.z = brv; acc.w = brv;
    #pragma unroll
    for (int c = 0; c < 32; c++) {
        float4 v = xp[(size_t)c*T_*(HW_/4)];
        float wc = w[c];
        acc.x += wc*v.x; acc.y += wc*v.y; acc.z += wc*v.z; acc.w += wc*v.w;
    }
    ((float4*)g_r)[tid] = acc;
}

// result = lerp_t(r) -> d_out tail — float4
__global__ void k_r2(float* __restrict__ out) {
    int tid = blockIdx.x*blockDim.x + threadIdx.x;   // 819200
    int hw4 = tid & 1023;
    int bt  = tid >> 10;                              // 0..799
    int t = bt % FT_;
    int b = bt / FT_;
    const float step = (float)(63.0/399.0);
    float pos = (float)t * step;
    int i0 = (int)pos;
    int i1 = min(i0+1, T_-1);
    float w = pos - (float)i0, w0 = 1.f - w;
    const float4* r0 = (const float4*)(g_r + (b*T_+i0)*HW_) + hw4;
    const float4* r1 = (const float4*)(g_r + (b*T_+i1)*HW_) + hw4;
    float4 a = *r0, c = *r1, v;
    v.x = a.x*w0 + c.x*w; v.y = a.y*w0 + c.y*w;
    v.z = a.z*w0 + c.z*w; v.w = a.w*w0 + c.w*w;
    ((float4*)(out + OUT_OFF_RESULT))[tid] = v;
}

// Per (b,n): gather x (32x64) -> f = Weff@xg (64x16, stored [t][o]) ->
// stats over lerped values in registers (no h store).
__global__ void k_gather(const float* __restrict__ x, const int* __restrict__ coord) {
    __shared__ float xg[C_*T_];      // [c][t]
    __shared__ float sWt[C_*CH_];    // transposed [c][o]
    __shared__ float sbe[CH_];
    __shared__ float sf[T_*CH_];     // [t][o]
    __shared__ float red[32*128];

    int bn = blockIdx.x;             // 1024
    int b = bn >> 9;
    int hcoord = coord[bn*2], wcoord = coord[bn*2+1];
    int idx = hcoord*64 + wcoord;

    const float* xp = x + (size_t)b*C_*T_*HW_ + idx;
    for (int e = threadIdx.x; e < C_*T_; e += 128)
        xg[e] = xp[(size_t)e * HW_];            // e = c*64+t
    for (int e = threadIdx.x; e < C_*CH_; e += 128) sWt[e] = g_Weff[e];
    if (threadIdx.x < CH_) sbe[threadIdx.x] = g_beff[threadIdx.x];
    __syncthreads();

    // phase 1: f[t][o] = beff[o] + sum_c Wt[c][o] * xg[c][t]; coalesced global store
    float4* gf = (float4*)(g_f + (size_t)bn*T_*CH_);
    for (int e = threadIdx.x; e < T_*CH_; e += 128) {
        int t = e >> 4, o = e & 15;
        float a = sbe[o];
        #pragma unroll
        for (int c = 0; c < 32; c++) a += sWt[c*CH_+o] * xg[c*64+t];
        sf[e] = a;
    }
    __syncthreads();
    // coalesced float4 store of sf -> g_f
    for (int e = threadIdx.x; e < T_*CH_/4; e += 128)
        gf[e] = ((const float4*)sf)[e];

    // phase 2: lerp to 400 in registers, accumulate stats only
    float s[CH_], q[CH_];
    #pragma unroll
    for (int o = 0; o < CH_; o++) { s[o] = 0.f; q[o] = 0.f; }
    const float step = (float)(63.0/399.0);
    for (int t = threadIdx.x; t < FT_; t += 128) {
        float pos = (float)t * step;
        int i0 = (int)pos;
        int i1 = min(i0+1, T_-1);
        float w = pos - (float)i0, w0 = 1.f - w;
        #pragma unroll
        for (int o = 0; o < CH_; o++) {
            float v = sf[i0*16+o]*w0 + sf[i1*16+o]*w;
            s[o] += v; q[o] += v*v;
        }
    }

    #pragma unroll
    for (int o = 0; o < CH_; o++) {
        red[o*128 + threadIdx.x]        = s[o];
        red[(CH_+o)*128 + threadIdx.x]  = q[o];
    }
    __syncthreads();
    if (threadIdx.x < 32) {
        float tot = 0.f;
        #pragma unroll 8
        for (int j = 0; j < 128; j++) tot += red[threadIdx.x*128 + j];
        g_part[bn*32 + threadIdx.x] = tot;
    }
}

// Reduce 1024 partials -> BN scale/shift (deterministic)
__global__ void k_stats(const float* __restrict__ gamma, const float* __restrict__ beta) {
    __shared__ float part[256];
    __shared__ float ss[32];
    int t = threadIdx.x;             // 256
    int col = t & 31, seg = t >> 5;
    float a = 0.f;
    #pragma unroll 4
    for (int j = seg*128; j < seg*128 + 128; j++) a += g_part[j*32 + col];
    part[t] = a;
    __syncthreads();
    if (t < 32) {
        float tot = 0.f;
        #pragma unroll
        for (int sg = 0; sg < 8; sg++) tot += part[sg*32 + t];
        ss[t] = tot;
    }
    __syncthreads();
    if (t < CH_) {
        float mean = ss[t] / (float)CNT_;
        float var  = ss[t+16] / (float)CNT_ - mean*mean;
        float sc = gamma[t] * rsqrtf(var + 1e-5f);
        g_scale[t] = sc;
        g_shift[t] = beta[t] - mean*sc;
    }
}

// lerp(f) + BN + ReLU + W2; out[b][o][t*N+n] coalesced. f reads are L2-resident.
__global__ void k_out(const float* __restrict__ W2, const float* __restrict__ b2,
                      float* __restrict__ out) {
    __shared__ float sW2[CH_*CH_], sb2[CH_], ssc[CH_], ssh[CH_];
    if (threadIdx.x < CH_*CH_) sW2[threadIdx.x] = W2[threadIdx.x];
    if (threadIdx.x < CH_) {
        sb2[threadIdx.x] = b2[threadIdx.x];
        ssc[threadIdx.x] = g_scale[threadIdx.x];
        ssh[threadIdx.x] = g_shift[threadIdx.x];
    }
    __syncthreads();
    int tid = blockIdx.x*blockDim.x + threadIdx.x;   // 409600
    int b = tid / L_;
    int l = tid - b*L_;
    int t = l >> 9, n = l & (N_-1);
    int bn = b*N_ + n;
    const float step = (float)(63.0/399.0);
    float pos = (float)t * step;
    int i0 = (int)pos;
    int i1 = min(i0+1, T_-1);
    float w = pos - (float)i0, w0 = 1.f - w;
    const float4* f0 = (const float4*)(g_f + ((size_t)bn*T_ + i0)*CH_);
    const float4* f1 = (const float4*)(g_f + ((size_t)bn*T_ + i1)*CH_);
    float4 a0=f0[0], a1=f0[1], a2=f0[2], a3=f0[3];
    float4 c0=f1[0], c1=f1[1], c2=f1[2], c3=f1[3];
    float hr[CH_];
    hr[0]=a0.x*w0+c0.x*w; hr[1]=a0.y*w0+c0.y*w; hr[2]=a0.z*w0+c0.z*w; hr[3]=a0.w*w0+c0.w*w;
    hr[4]=a1.x*w0+c1.x*w; hr[5]=a1.y*w0+c1.y*w; hr[6]=a1.z*w0+c1.z*w; hr[7]=a1.w*w0+c1.w*w;
    hr[8]=a2.x*w0+c2.x*w; hr[9]=a2.y*w0+c2.y*w; hr[10]=a2.z*w0+c2.z*w; hr[11]=a2.w*w0+c2.w*w;
    hr[12]=a3.x*w0+c3.x*w; hr[13]=a3.y*w0+c3.y*w; hr[14]=a3.z*w0+c3.z*w; hr[15]=a3.w*w0+c3.w*w;
    #pragma unroll
    for (int o = 0; o < CH_; o++) hr[o] = fmaxf(ssc[o]*hr[o] + ssh[o], 0.f);
    #pragma unroll
    for (int o2 = 0; o2 < CH_; o2++) {
        float acc = sb2[o2];
        #pragma unroll
        for (int o = 0; o < CH_; o++) acc += sW2[o2*16+o] * hr[o];
        out[((size_t)(b*CH_+o2))*L_ + l] = acc;
    }
}

extern "C" void kernel_launch(void* const* d_in, const int* in_sizes, int n_in,
                              void* d_out, int out_size) {
    const float* x     = (const float*)d_in[0];
    const int*   coord = (const int*)  d_in[1];
    const float* Wf    = (const float*)d_in[2];
    const float* bf    = (const float*)d_in[3];
    const float* Wr    = (const float*)d_in[4];
    const float* br    = (const float*)d_in[5];
    const float* W1    = (const float*)d_in[6];
    const float* b1    = (const float*)d_in[7];
    const float* gamma = (const float*)d_in[8];
    const float* beta  = (const float*)d_in[9];
    const float* W2    = (const float*)d_in[10];
    const float* b2    = (const float*)d_in[11];
    float* out = (float*)d_out;

    k_init  <<<1,    512>>>(W1, Wf, b1, bf);
    k_r     <<<512,  256>>>(x, Wr, br);        // streams x, warms L2 for the gather
    k_gather<<<1024, 128>>>(x, coord);         // scattered reads mostly L2 hits
    k_r2    <<<3200, 256>>>(out);
    k_stats <<<1,    256>>>(gamma, beta);
    k_out   <<<1600, 256>>>(W2, b2, out);
}

// round 3
// speedup vs baseline: 1.0168x; 1.0168x over previous
#include <cuda_runtime.h>

#define B_   2
#define C_   32
#define T_   64
#define HW_  4096
#define N_   512
#define BN_  (B_*N_)         /* 1024 */
#define CH_  16
#define FT_  400
#define L_   (FT_*N_)        /* 204800 */
#define CNT_ (B_*L_)         /* 409600 */
#define OUT_OFF_RESULT ((size_t)B_*CH_*L_)  /* 6,553,600 */

// ---- scratch (device globals) ----
__device__ __align__(16) float g_r[B_*T_*HW_];            // 2 MB
__device__ __align__(16) float g_f[(size_t)T_*BN_*CH_];   // 4 MB, layout [t][bn][o]
__device__ float g_part[BN_*32];
__device__ float g_scale[CH_];
__device__ float g_shift[CH_];

// ---- branch A: result path ----
// r[b][t][hw] = Wr . x[b][:][t][hw] + br  (float4, streams x)
__global__ void k_r(const float* __restrict__ x, const float* __restrict__ Wr,
                    const float* __restrict__ br) {
    __shared__ float w[32];
    if (threadIdx.x < 32) w[threadIdx.x] = Wr[threadIdx.x];
    __syncthreads();
    int tid = blockIdx.x*blockDim.x + threadIdx.x;   // 131072
    int hw4 = tid & 1023;
    int bt  = tid >> 10;
    int b = bt >> 6, t = bt & 63;
    const float4* xp = (const float4*)(x + (size_t)(b*C_*T_ + t)*HW_) + hw4;
    float brv = br[0];
    float4 acc = make_float4(brv, brv, brv, brv);
    #pragma unroll
    for (int c = 0; c < 32; c++) {
        float4 v = xp[(size_t)c*T_*(HW_/4)];
        float wc = w[c];
        acc.x += wc*v.x; acc.y += wc*v.y; acc.z += wc*v.z; acc.w += wc*v.w;
    }
    ((float4*)g_r)[tid] = acc;
}

// result = lerp_t(r) -> d_out tail
__global__ void k_r2(float* __restrict__ out) {
    int tid = blockIdx.x*blockDim.x + threadIdx.x;   // 819200
    int hw4 = tid & 1023;
    int bt  = tid >> 10;                              // 0..799
    int t = bt % FT_;
    int b = bt / FT_;
    const float step = (float)(63.0/399.0);
    float pos = (float)t * step;
    int i0 = (int)pos;
    int i1 = min(i0+1, T_-1);
    float w = pos - (float)i0, w0 = 1.f - w;
    float4 a = ((const float4*)(g_r + (b*T_+i0)*HW_))[hw4];
    float4 c = ((const float4*)(g_r + (b*T_+i1)*HW_))[hw4];
    float4 v = make_float4(a.x*w0 + c.x*w, a.y*w0 + c.y*w,
                           a.z*w0 + c.z*w, a.w*w0 + c.w*w);
    ((float4*)(out + OUT_OFF_RESULT))[tid] = v;
}

// ---- branch B: sample path ----
// Per (b,n): gather x (32x64), fold W1@Wf inline, f = Weff@xg -> g_f[t][bn][o],
// stats over lerped values in registers.
__global__ void k_gather(const float* __restrict__ x, const int* __restrict__ coord,
                         const float* __restrict__ W1, const float* __restrict__ Wf,
                         const float* __restrict__ b1, const float* __restrict__ bf) {
    __shared__ float xg[C_*T_];      // [c][t] 8 KB
    __shared__ float sWt[C_*CH_];    // transposed [c][o]
    __shared__ float sbe[CH_];
    __shared__ float sf[T_*CH_];     // [t][o] 4 KB
    __shared__ float red[32*128];    // 16 KB; also stages W1/Wf/bf up front

    int bn = blockIdx.x;             // 1024
    int b = bn >> 9;
    int tid = threadIdx.x;
    int idx = coord[bn*2]*64 + coord[bn*2+1];

    // issue the 16 scattered x loads early (max MLP), consume later
    const float* xp = x + (size_t)b*C_*T_*HW_ + idx;
    float rv[16];
    #pragma unroll
    for (int i = 0; i < 16; i++)
        rv[i] = xp[(size_t)(tid + i*128) * HW_];

    // stage W1 (512), Wf (1024), bf (32) into red[]
    for (int e = tid; e < CH_*C_; e += 128) red[e] = W1[e];
    for (int e = tid; e < C_*C_; e += 128) red[512 + e] = Wf[e];
    if (tid < 32) red[1536 + tid] = bf[tid];
    __syncthreads();

    // fold: sWt[c][o] = sum_k W1[o][k] * Wf[k][c]
    #pragma unroll
    for (int i = 0; i < 4; i++) {
        int e = tid*4 + i;           // 0..511
        int c = e >> 4, o = e & 15;
        float a = 0.f;
        #pragma unroll
        for (int k = 0; k < 32; k++) a += red[o*32+k] * red[512 + k*32 + c];
        sWt[c*CH_+o] = a;
    }
    if (tid < CH_) {
        float bb = b1[tid];
        #pragma unroll
        for (int k = 0; k < 32; k++) bb += red[tid*32+k] * red[1536+k];
        sbe[tid] = bb;
    }
    // park gathered x into smem (no sync needed before: xg untouched so far)
    #pragma unroll
    for (int i = 0; i < 16; i++) xg[tid + i*128] = rv[i];
    __syncthreads();

    // phase 1: f[t][o] = beff[o] + sum_c Wt[c][o] * xg[c][t]
    #pragma unroll
    for (int i = 0; i < 8; i++) {
        int e = tid + i*128;         // 0..1023
        int t = e >> 4, o = e & 15;
        float a = sbe[o];
        #pragma unroll
        for (int c = 0; c < 32; c++) a += sWt[c*CH_+o] * xg[c*64+t];
        sf[e] = a;
    }
    __syncthreads();

    // store f to global in [t][bn][o] layout (float4 chunks of o)
    {
        float4* gf4 = (float4*)g_f;
        const float4* sf4 = (const float4*)sf;
        #pragma unroll
        for (int i = 0; i < 2; i++) {
            int e4 = tid + i*128;    // 0..255
            int t = e4 >> 2, oq = e4 & 3;
            gf4[((size_t)t*BN_ + bn)*4 + oq] = sf4[e4];
        }
    }

    // phase 2: lerp to 400 in registers, accumulate stats only
    float s[CH_], q[CH_];
    #pragma unroll
    for (int o = 0; o < CH_; o++) { s[o] = 0.f; q[o] = 0.f; }
    const float step = (float)(63.0/399.0);
    for (int t = tid; t < FT_; t += 128) {
        float pos = (float)t * step;
        int i0 = (int)pos;
        int i1 = min(i0+1, T_-1);
        float w = pos - (float)i0, w0 = 1.f - w;
        #pragma unroll
        for (int o = 0; o < CH_; o++) {
            float v = sf[i0*16+o]*w0 + sf[i1*16+o]*w;
            s[o] += v; q[o] += v*v;
        }
    }
    __syncthreads();   // red[] reuse
    #pragma unroll
    for (int o = 0; o < CH_; o++) {
        red[o*128 + tid]        = s[o];
        red[(CH_+o)*128 + tid]  = q[o];
    }
    __syncthreads();
    if (tid < 32) {
        float tot = 0.f;
        #pragma unroll 8
        for (int j = 0; j < 128; j++) tot += red[tid*128 + j];
        g_part[bn*32 + tid] = tot;
    }
}

// Reduce 1024 partials -> BN scale/shift (deterministic)
__global__ void k_stats(const float* __restrict__ gamma, const float* __restrict__ beta) {
    __shared__ float part[256];
    __shared__ float ss[32];
    int t = threadIdx.x;             // 256
    int col = t & 31, seg = t >> 5;
    float a = 0.f;
    #pragma unroll 4
    for (int j = seg*128; j < seg*128 + 128; j++) a += g_part[j*32 + col];
    part[t] = a;
    __syncthreads();
    if (t < 32) {
        float tot = 0.f;
        #pragma unroll
        for (int sg = 0; sg < 8; sg++) tot += part[sg*32 + t];
        ss[t] = tot;
    }
    __syncthreads();
    if (t < CH_) {
        float mean = ss[t] / (float)CNT_;
        float var  = ss[t+16] / (float)CNT_ - mean*mean;
        float sc = gamma[t] * rsqrtf(var + 1e-5f);
        g_scale[t] = sc;
        g_shift[t] = beta[t] - mean*sc;
    }
}

// lerp(f) + BN + ReLU + W2; f reads now fully coalesced ([t][bn][o] layout).
__global__ void k_out(const float* __restrict__ W2, const float* __restrict__ b2,
                      float* __restrict__ out) {
    __shared__ float sW2[CH_*CH_], sb2[CH_], ssc[CH_], ssh[CH_];
    if (threadIdx.x < CH_*CH_) sW2[threadIdx.x] = W2[threadIdx.x];
    if (threadIdx.x < CH_) {
        sb2[threadIdx.x] = b2[threadIdx.x];
        ssc[threadIdx.x] = g_scale[threadIdx.x];
        ssh[threadIdx.x] = g_shift[threadIdx.x];
    }
    __syncthreads();
    int tid = blockIdx.x*blockDim.x + threadIdx.x;   // 409600
    int b = tid / L_;
    int l = tid - b*L_;
    int t = l >> 9, n = l & (N_-1);
    int bn = b*N_ + n;
    const float step = (float)(63.0/399.0);
    float pos = (float)t * step;
    int i0 = (int)pos;
    int i1 = min(i0+1, T_-1);
    float w = pos - (float)i0, w0 = 1.f - w;
    const float4* f0 = (const float4*)(g_f + ((size_t)i0*BN_ + bn)*CH_);
    const float4* f1 = (const float4*)(g_f + ((size_t)i1*BN_ + bn)*CH_);
    float4 a0=f0[0], a1=f0[1], a2=f0[2], a3=f0[3];
    float4 c0=f1[0], c1=f1[1], c2=f1[2], c3=f1[3];
    float hr[CH_];
    hr[0]=a0.x*w0+c0.x*w; hr[1]=a0.y*w0+c0.y*w; hr[2]=a0.z*w0+c0.z*w; hr[3]=a0.w*w0+c0.w*w;
    hr[4]=a1.x*w0+c1.x*w; hr[5]=a1.y*w0+c1.y*w; hr[6]=a1.z*w0+c1.z*w; hr[7]=a1.w*w0+c1.w*w;
    hr[8]=a2.x*w0+c2.x*w; hr[9]=a2.y*w0+c2.y*w; hr[10]=a2.z*w0+c2.z*w; hr[11]=a2.w*w0+c2.w*w;
    hr[12]=a3.x*w0+c3.x*w; hr[13]=a3.y*w0+c3.y*w; hr[14]=a3.z*w0+c3.z*w; hr[15]=a3.w*w0+c3.w*w;
    #pragma unroll
    for (int o = 0; o < CH_; o++) hr[o] = fmaxf(ssc[o]*hr[o] + ssh[o], 0.f);
    #pragma unroll
    for (int o2 = 0; o2 < CH_; o2++) {
        float acc = sb2[o2];
        #pragma unroll
        for (int o = 0; o < CH_; o++) acc += sW2[o2*16+o] * hr[o];
        out[((size_t)(b*CH_+o2))*L_ + l] = acc;
    }
}

extern "C" void kernel_launch(void* const* d_in, const int* in_sizes, int n_in,
                              void* d_out, int out_size) {
    const float* x     = (const float*)d_in[0];
    const int*   coord = (const int*)  d_in[1];
    const float* Wf    = (const float*)d_in[2];
    const float* bf    = (const float*)d_in[3];
    const float* Wr    = (const float*)d_in[4];
    const float* br    = (const float*)d_in[5];
    const float* W1    = (const float*)d_in[6];
    const float* b1    = (const float*)d_in[7];
    const float* gamma = (const float*)d_in[8];
    const float* beta  = (const float*)d_in[9];
    const float* W2    = (const float*)d_in[10];
    const float* b2    = (const float*)d_in[11];
    float* out = (float*)d_out;

    // lazily created side stream + events (host objects only; same work every call)
    static cudaStream_t s2 = nullptr;
    static cudaEvent_t eFork = nullptr, eJoin = nullptr;
    if (!s2) {
        cudaStreamCreateWithFlags(&s2, cudaStreamNonBlocking);
        cudaEventCreateWithFlags(&eFork, cudaEventDisableTiming);
        cudaEventCreateWithFlags(&eJoin, cudaEventDisableTiming);
    }

    // fork branch A (result path) onto s2
    cudaEventRecord(eFork, 0);
    cudaStreamWaitEvent(s2, eFork, 0);
    k_r <<<512,  256, 0, s2>>>(x, Wr, br);
    k_r2<<<3200, 256, 0, s2>>>(out);
    cudaEventRecord(eJoin, s2);

    // branch B (sample path) on the captured stream
    k_gather<<<1024, 128>>>(x, coord, W1, Wf, b1, bf);
    k_stats <<<1,    256>>>(gamma, beta);
    k_out   <<<1600, 256>>>(W2, b2, out);

    // join
    cudaStreamWaitEvent(0, eJoin, 0);
}

// round 4
// speedup vs baseline: 1.1084x; 1.0900x over previous
#include <cuda_runtime.h>

#define B_   2
#define C_   32
#define T_   64
#define HW_  4096
#define N_   512
#define BN_  (B_*N_)         /* 1024 */
#define CH_  16
#define FT_  400
#define L_   (FT_*N_)        /* 204800 */
#define CNT_ (B_*L_)         /* 409600 */
#define OUT_OFF_RESULT ((size_t)B_*CH_*L_)  /* 6,553,600 */

// ---- scratch (device globals) ----
__device__ __align__(16) float g_r[B_*T_*HW_];            // 2 MB
__device__ __align__(16) float g_f[(size_t)T_*BN_*CH_];   // 4 MB, layout [t][bn][o]
__device__ __align__(16) float g_part[32*BN_];            // [col][block] transposed
__device__ float g_ss[32];                                // sums[16] + sumsqs[16]

// ============================================================================
// K1: blocks [0,1024) -> r path (Wr.x stream); blocks [1024,2048) -> gather path
// ============================================================================
__global__ void __launch_bounds__(128) k_main(
    const float* __restrict__ x, const int* __restrict__ coord,
    const float* __restrict__ Wr, const float* __restrict__ br,
    const float* __restrict__ W1, const float* __restrict__ Wf,
    const float* __restrict__ b1, const float* __restrict__ bf)
{
    __shared__ float xg[C_*T_];      // [c][t] 8 KB (r path: [0..31]=Wr)
    __shared__ float sWt[C_*CH_];    // transposed [c][o]
    __shared__ float sbe[CH_];
    __shared__ float sf[T_*CH_];     // [t][o]
    __shared__ float red[32*128];    // reduction + W1/Wf/bf staging

    int bid = blockIdx.x;
    int tid = threadIdx.x;

    if (bid < 1024) {
        // ---- r path: r[b][t][hw] = Wr . x + br, float4 over hw ----
        if (tid < 32) xg[tid] = Wr[tid];
        __syncthreads();
        int gt = bid*128 + tid;            // 131072 threads, 4 hw each
        int hw4 = gt & 1023;
        int bt  = gt >> 10;
        int b = bt >> 6, t = bt & 63;
        const float4* xp = (const float4*)(x + (size_t)(b*C_*T_ + t)*HW_) + hw4;
        float brv = br[0];
        float4 acc = make_float4(brv, brv, brv, brv);
        #pragma unroll
        for (int c = 0; c < 32; c++) {
            float4 v = xp[(size_t)c*T_*(HW_/4)];
            float wc = xg[c];
            acc.x += wc*v.x; acc.y += wc*v.y; acc.z += wc*v.z; acc.w += wc*v.w;
        }
        ((float4*)g_r)[gt] = acc;
        return;
    }

    // ---- gather path ----
    int bn = bid - 1024;                   // 0..1023
    int b = bn >> 9;
    int idx = coord[bn*2]*64 + coord[bn*2+1];

    // issue 16 scattered x loads early (max MLP)
    const float* xp = x + (size_t)b*C_*T_*HW_ + idx;
    float rv[16];
    #pragma unroll
    for (int i = 0; i < 16; i++)
        rv[i] = xp[(size_t)(tid + i*128) * HW_];

    // stage W1 (512), Wf (1024), bf (32) in red[]
    for (int e = tid; e < CH_*C_; e += 128) red[e] = W1[e];
    for (int e = tid; e < C_*C_; e += 128) red[512 + e] = Wf[e];
    if (tid < 32) red[1536 + tid] = bf[tid];
    __syncthreads();

    // fold: sWt[c][o] = sum_k W1[o][k] * Wf[k][c]
    #pragma unroll
    for (int i = 0; i < 4; i++) {
        int e = tid*4 + i;
        int c = e >> 4, o = e & 15;
        float a = 0.f;
        #pragma unroll
        for (int k = 0; k < 32; k++) a += red[o*32+k] * red[512 + k*32 + c];
        sWt[c*CH_+o] = a;
    }
    if (tid < CH_) {
        float bb = b1[tid];
        #pragma unroll
        for (int k = 0; k < 32; k++) bb += red[tid*32+k] * red[1536+k];
        sbe[tid] = bb;
    }
    #pragma unroll
    for (int i = 0; i < 16; i++) xg[tid + i*128] = rv[i];
    __syncthreads();

    // f[t][o] = beff[o] + sum_c Wt[c][o] * xg[c][t]
    #pragma unroll
    for (int i = 0; i < 8; i++) {
        int e = tid + i*128;
        int t = e >> 4, o = e & 15;
        float a = sbe[o];
        #pragma unroll
        for (int c = 0; c < 32; c++) a += sWt[c*CH_+o] * xg[c*64+t];
        sf[e] = a;
    }
    __syncthreads();

    // store f -> g_f in [t][bn][o] layout (float4 over o)
    {
        float4* gf4 = (float4*)g_f;
        const float4* sf4 = (const float4*)sf;
        #pragma unroll
        for (int i = 0; i < 2; i++) {
            int e4 = tid + i*128;
            int t = e4 >> 2, oq = e4 & 3;
            gf4[((size_t)t*BN_ + bn)*4 + oq] = sf4[e4];
        }
    }

    // lerp to 400 in registers, accumulate stats
    float s[CH_], q[CH_];
    #pragma unroll
    for (int o = 0; o < CH_; o++) { s[o] = 0.f; q[o] = 0.f; }
    const float step = (float)(63.0/399.0);
    for (int t = tid; t < FT_; t += 128) {
        float pos = (float)t * step;
        int i0 = (int)pos;
        int i1 = min(i0+1, T_-1);
        float w = pos - (float)i0, w0 = 1.f - w;
        #pragma unroll
        for (int o = 0; o < CH_; o++) {
            float v = sf[i0*16+o]*w0 + sf[i1*16+o]*w;
            s[o] += v; q[o] += v*v;
        }
    }
    __syncthreads();   // red[] reuse
    #pragma unroll
    for (int o = 0; o < CH_; o++) {
        red[o*128 + tid]        = s[o];
        red[(CH_+o)*128 + tid]  = q[o];
    }
    __syncthreads();
    if (tid < 32) {
        float tot = 0.f;
        #pragma unroll 8
        for (int j = 0; j < 128; j++) tot += red[tid*128 + j];
        g_part[tid*BN_ + bn] = tot;        // transposed: [col][block]
    }
}

// ============================================================================
// K2: 32 blocks, block c reduces g_part[c][0..1023] (coalesced float4) -> g_ss[c]
// ============================================================================
__global__ void __launch_bounds__(256) k_stats() {
    __shared__ float sm[256];
    int c = blockIdx.x;
    float4 v = ((const float4*)(g_part + c*BN_))[threadIdx.x];
    sm[threadIdx.x] = (v.x + v.y) + (v.z + v.w);
    __syncthreads();
    #pragma unroll
    for (int sft = 128; sft > 0; sft >>= 1) {
        if (threadIdx.x < sft) sm[threadIdx.x] += sm[threadIdx.x + sft];
        __syncthreads();
    }
    if (threadIdx.x == 0) g_ss[c] = sm[0];
}

// ============================================================================
// K3: blocks [0,3200) -> result lerp; blocks [3200,4800) -> BN+ReLU+W2 epilogue
// ============================================================================
__global__ void __launch_bounds__(256) k_fin(
    const float* __restrict__ gamma, const float* __restrict__ beta,
    const float* __restrict__ W2, const float* __restrict__ b2,
    float* __restrict__ out)
{
    __shared__ float sW2[CH_*CH_], sb2[CH_], ssc[CH_], ssh[CH_];

    if (blockIdx.x < 3200) {
        // ---- result = lerp_t(r) ----
        int tid = blockIdx.x*256 + threadIdx.x;      // 819200
        int hw4 = tid & 1023;
        int bt  = tid >> 10;
        int t = bt % FT_;
        int b = bt / FT_;
        const float step = (float)(63.0/399.0);
        float pos = (float)t * step;
        int i0 = (int)pos;
        int i1 = min(i0+1, T_-1);
        float w = pos - (float)i0, w0 = 1.f - w;
        float4 a = ((const float4*)(g_r + (b*T_+i0)*HW_))[hw4];
        float4 c = ((const float4*)(g_r + (b*T_+i1)*HW_))[hw4];
        float4 v = make_float4(a.x*w0 + c.x*w, a.y*w0 + c.y*w,
                               a.z*w0 + c.z*w, a.w*w0 + c.w*w);
        ((float4*)(out + OUT_OFF_RESULT))[tid] = v;
        return;
    }

    // ---- epilogue: lerp(f) + BN + ReLU + W2 ----
    if (threadIdx.x < CH_*CH_) sW2[threadIdx.x] = W2[threadIdx.x];
    if (threadIdx.x < CH_) {
        int o = threadIdx.x;
        sb2[o] = b2[o];
        float mean = g_ss[o]    * (1.f/(float)CNT_);
        float var  = g_ss[o+16] * (1.f/(float)CNT_) - mean*mean;
        float sc = gamma[o] * rsqrtf(var + 1e-5f);
        ssc[o] = sc;
        ssh[o] = beta[o] - mean*sc;
    }
    __syncthreads();
    int tid = (blockIdx.x - 3200)*256 + threadIdx.x;  // 409600
    int b = tid / L_;
    int l = tid - b*L_;
    int t = l >> 9, n = l & (N_-1);
    int bn = b*N_ + n;
    const float step = (float)(63.0/399.0);
    float pos = (float)t * step;
    int i0 = (int)pos;
    int i1 = min(i0+1, T_-1);
    float w = pos - (float)i0, w0 = 1.f - w;
    const float4* f0 = (const float4*)(g_f + ((size_t)i0*BN_ + bn)*CH_);
    const float4* f1 = (const float4*)(g_f + ((size_t)i1*BN_ + bn)*CH_);
    float4 a0=f0[0], a1=f0[1], a2=f0[2], a3=f0[3];
    float4 c0=f1[0], c1=f1[1], c2=f1[2], c3=f1[3];
    float hr[CH_];
    hr[0]=a0.x*w0+c0.x*w; hr[1]=a0.y*w0+c0.y*w; hr[2]=a0.z*w0+c0.z*w; hr[3]=a0.w*w0+c0.w*w;
    hr[4]=a1.x*w0+c1.x*w; hr[5]=a1.y*w0+c1.y*w; hr[6]=a1.z*w0+c1.z*w; hr[7]=a1.w*w0+c1.w*w;
    hr[8]=a2.x*w0+c2.x*w; hr[9]=a2.y*w0+c2.y*w; hr[10]=a2.z*w0+c2.z*w; hr[11]=a2.w*w0+c2.w*w;
    hr[12]=a3.x*w0+c3.x*w; hr[13]=a3.y*w0+c3.y*w; hr[14]=a3.z*w0+c3.z*w; hr[15]=a3.w*w0+c3.w*w;
    #pragma unroll
    for (int o = 0; o < CH_; o++) hr[o] = fmaxf(ssc[o]*hr[o] + ssh[o], 0.f);
    #pragma unroll
    for (int o2 = 0; o2 < CH_; o2++) {
        float acc = sb2[o2];
        #pragma unroll
        for (int o = 0; o < CH_; o++) acc += sW2[o2*16+o] * hr[o];
        out[((size_t)(b*CH_+o2))*L_ + l] = acc;
    }
}

extern "C" void kernel_launch(void* const* d_in, const int* in_sizes, int n_in,
                              void* d_out, int out_size) {
    const float* x     = (const float*)d_in[0];
    const int*   coord = (const int*)  d_in[1];
    const float* Wf    = (const float*)d_in[2];
    const float* bf    = (const float*)d_in[3];
    const float* Wr    = (const float*)d_in[4];
    const float* br    = (const float*)d_in[5];
    const float* W1    = (const float*)d_in[6];
    const float* b1    = (const float*)d_in[7];
    const float* gamma = (const float*)d_in[8];
    const float* beta  = (const float*)d_in[9];
    const float* W2    = (const float*)d_in[10];
    const float* b2    = (const float*)d_in[11];
    float* out = (float*)d_out;

    k_main <<<2048, 128>>>(x, coord, Wr, br, W1, Wf, b1, bf);
    k_stats<<<32,   256>>>();
    k_fin  <<<4800, 256>>>(gamma, beta, W2, b2, out);
}

// round 5
// speedup vs baseline: 1.5216x; 1.3728x over previous
#include <cuda_runtime.h>

#define B_   2
#define C_   32
#define T_   64
#define HW_  4096
#define N_   512
#define BN_  (B_*N_)         /* 1024 */
#define CH_  16
#define FT_  400
#define L_   (FT_*N_)        /* 204800 */
#define CNT_ (B_*L_)         /* 409600 */
#define OUT_OFF_RESULT ((size_t)B_*CH_*L_)  /* 6,553,600 */

// ---- scratch (device globals) ----
__device__ __align__(16) float g_r[B_*T_*HW_];            // 2 MB
__device__ __align__(16) float g_f[(size_t)T_*BN_*CH_];   // 4 MB, layout [t][bn][o]
__device__ __align__(16) float g_part[32*BN_];            // [col][block]
__device__ float g_ss[32];                                // sums[16] + sumsqs[16]

// ============================================================================
// K1: blocks [0,1024) -> gather path; blocks [1024,2048) -> r stream path
// ============================================================================
__global__ void __launch_bounds__(128, 8) k_main(
    const float* __restrict__ x, const int* __restrict__ coord,
    const float* __restrict__ Wr, const float* __restrict__ br,
    const float* __restrict__ W1, const float* __restrict__ Wf,
    const float* __restrict__ b1, const float* __restrict__ bf)
{
    __shared__ float xg[C_*T_];      // 8 KB: gather x [c][t]; also Wf stage; r path: Wr
    __shared__ float sWt[C_*CH_];    // 2 KB: folded weights [c][o]
    __shared__ float sbe[CH_];
    __shared__ float sf[T_*CH_];     // 4 KB: f [t][o]; also W1 stage
    __shared__ float red[4*32];      // warp partials
    __shared__ float sbf[C_];

    int bid = blockIdx.x;
    int tid = threadIdx.x;

    if (bid >= 1024) {
        // ---- r path: r[b][t][hw] = Wr . x + br, batched float4 loads ----
        if (tid < 32) xg[tid] = Wr[tid];
        __syncthreads();
        int gt = (bid - 1024)*128 + tid;   // 131072 threads, 4 hw each
        int hw4 = gt & 1023;
        int bt  = gt >> 10;
        int b = bt >> 6, t = bt & 63;
        const float4* xp = (const float4*)(x + (size_t)(b*C_*T_ + t)*HW_) + hw4;
        float brv = br[0];
        float4 acc = make_float4(brv, brv, brv, brv);
        #pragma unroll
        for (int cc = 0; cc < 4; cc++) {
            float4 v[8];
            #pragma unroll
            for (int j = 0; j < 8; j++)
                v[j] = xp[(size_t)(cc*8+j)*T_*(HW_/4)];
            #pragma unroll
            for (int j = 0; j < 8; j++) {
                float wc = xg[cc*8+j];
                acc.x += wc*v[j].x; acc.y += wc*v[j].y;
                acc.z += wc*v[j].z; acc.w += wc*v[j].w;
            }
        }
        ((float4*)g_r)[gt] = acc;
        return;
    }

    // ---- gather path ----
    int bn = bid;                          // 0..1023
    int b = bn >> 9;
    int idx = coord[bn*2]*64 + coord[bn*2+1];

    // issue 16 scattered x loads early (max MLP)
    const float* xp = x + (size_t)b*C_*T_*HW_ + idx;
    float rv[16];
    #pragma unroll
    for (int i = 0; i < 16; i++)
        rv[i] = xp[(size_t)(tid + i*128) * HW_];

    // stage W1 -> sf[0:512], Wf -> xg[0:1024], bf -> sbf
    for (int e = tid; e < CH_*C_; e += 128) sf[e] = W1[e];
    for (int e = tid; e < C_*C_; e += 128) xg[e] = Wf[e];
    if (tid < 32) sbf[tid] = bf[tid];
    __syncthreads();

    // fold: sWt[c][o] = sum_k W1[o][k] * Wf[k][c]
    #pragma unroll
    for (int i = 0; i < 4; i++) {
        int e = tid*4 + i;
        int c = e >> 4, o = e & 15;
        float a = 0.f;
        #pragma unroll
        for (int k = 0; k < 32; k++) a += sf[o*32+k] * xg[k*32 + c];
        sWt[c*CH_+o] = a;
    }
    if (tid < CH_) {
        float bb = b1[tid];
        #pragma unroll
        for (int k = 0; k < 32; k++) bb += sf[tid*32+k] * sbf[k];
        sbe[tid] = bb;
    }
    __syncthreads();   // fold done reading stages
    #pragma unroll
    for (int i = 0; i < 16; i++) xg[tid + i*128] = rv[i];   // park x [c][t]
    __syncthreads();

    // f[t][o] = beff[o] + sum_c Wt[c][o] * xg[c][t]  (overwrites W1 stage)
    #pragma unroll
    for (int i = 0; i < 8; i++) {
        int e = tid + i*128;
        int t = e >> 4, o = e & 15;
        float a = sbe[o];
        #pragma unroll
        for (int c = 0; c < 32; c++) a += sWt[c*CH_+o] * xg[c*64+t];
        sf[e] = a;
    }
    __syncthreads();

    // store f -> g_f in [t][bn][o] layout (float4 over o)
    {
        float4* gf4 = (float4*)g_f;
        const float4* sf4 = (const float4*)sf;
        #pragma unroll
        for (int i = 0; i < 2; i++) {
            int e4 = tid + i*128;
            int t = e4 >> 2, oq = e4 & 3;
            gf4[((size_t)t*BN_ + bn)*4 + oq] = sf4[e4];
        }
    }

    // lerp to 400 in registers, accumulate stats
    float s[CH_], q[CH_];
    #pragma unroll
    for (int o = 0; o < CH_; o++) { s[o] = 0.f; q[o] = 0.f; }
    const float step = (float)(63.0/399.0);
    for (int t = tid; t < FT_; t += 128) {
        float pos = (float)t * step;
        int i0 = (int)pos;
        int i1 = min(i0+1, T_-1);
        float w = pos - (float)i0, w0 = 1.f - w;
        #pragma unroll
        for (int o = 0; o < CH_; o++) {
            float v = sf[i0*16+o]*w0 + sf[i1*16+o]*w;
            s[o] += v; q[o] += v*v;
        }
    }
    // warp butterfly reduction (deterministic tree)
    #pragma unroll
    for (int o = 0; o < CH_; o++) {
        #pragma unroll
        for (int sh = 16; sh > 0; sh >>= 1) {
            s[o] += __shfl_xor_sync(0xffffffffu, s[o], sh);
            q[o] += __shfl_xor_sync(0xffffffffu, q[o], sh);
        }
    }
    int warp = tid >> 5, lane = tid & 31;
    if (lane == 0) {
        #pragma unroll
        for (int o = 0; o < CH_; o++) {
            red[warp*32 + o]      = s[o];
            red[warp*32 + 16 + o] = q[o];
        }
    }
    __syncthreads();
    if (tid < 32)
        g_part[tid*BN_ + bn] = red[tid] + red[32+tid] + red[64+tid] + red[96+tid];
}

// ============================================================================
// K2: 32 blocks, block c reduces g_part[c][0..1023] -> g_ss[c]
// ============================================================================
__global__ void __launch_bounds__(256) k_stats() {
    __shared__ float sm[256];
    int c = blockIdx.x;
    float4 v = ((const float4*)(g_part + c*BN_))[threadIdx.x];
    sm[threadIdx.x] = (v.x + v.y) + (v.z + v.w);
    __syncthreads();
    #pragma unroll
    for (int sft = 128; sft > 0; sft >>= 1) {
        if (threadIdx.x < sft) sm[threadIdx.x] += sm[threadIdx.x + sft];
        __syncthreads();
    }
    if (threadIdx.x == 0) g_ss[c] = sm[0];
}

// ============================================================================
// K3: blocks [0,3200) -> result lerp; blocks [3200,4800) -> BN+ReLU+W2 epilogue
// ============================================================================
__global__ void __launch_bounds__(256) k_fin(
    const float* __restrict__ gamma, const float* __restrict__ beta,
    const float* __restrict__ W2, const float* __restrict__ b2,
    float* __restrict__ out)
{
    __shared__ float sW2[CH_*CH_], sb2[CH_], ssc[CH_], ssh[CH_];

    if (blockIdx.x < 3200) {
        // ---- result = lerp_t(r) ----
        int tid = blockIdx.x*256 + threadIdx.x;      // 819200
        int hw4 = tid & 1023;
        int bt  = tid >> 10;
        int t = bt % FT_;
        int b = bt / FT_;
        const float step = (float)(63.0/399.0);
        float pos = (float)t * step;
        int i0 = (int)pos;
        int i1 = min(i0+1, T_-1);
        float w = pos - (float)i0, w0 = 1.f - w;
        float4 a = ((const float4*)(g_r + (b*T_+i0)*HW_))[hw4];
        float4 c = ((const float4*)(g_r + (b*T_+i1)*HW_))[hw4];
        float4 v = make_float4(a.x*w0 + c.x*w, a.y*w0 + c.y*w,
                               a.z*w0 + c.z*w, a.w*w0 + c.w*w);
        ((float4*)(out + OUT_OFF_RESULT))[tid] = v;
        return;
    }

    // ---- epilogue: lerp(f) + BN + ReLU + W2 ----
    if (threadIdx.x < CH_*CH_) sW2[threadIdx.x] = W2[threadIdx.x];
    if (threadIdx.x < CH_) {
        int o = threadIdx.x;
        sb2[o] = b2[o];
        float mean = g_ss[o]    * (1.f/(float)CNT_);
        float var  = g_ss[o+16] * (1.f/(float)CNT_) - mean*mean;
        float sc = gamma[o] * rsqrtf(var + 1e-5f);
        ssc[o] = sc;
        ssh[o] = beta[o] - mean*sc;
    }
    __syncthreads();
    int tid = (blockIdx.x - 3200)*256 + threadIdx.x;  // 409600
    int b = tid / L_;
    int l = tid - b*L_;
    int t = l >> 9, n = l & (N_-1);
    int bn = b*N_ + n;
    const float step = (float)(63.0/399.0);
    float pos = (float)t * step;
    int i0 = (int)pos;
    int i1 = min(i0+1, T_-1);
    float w = pos - (float)i0, w0 = 1.f - w;
    const float4* f0 = (const float4*)(g_f + ((size_t)i0*BN_ + bn)*CH_);
    const float4* f1 = (const float4*)(g_f + ((size_t)i1*BN_ + bn)*CH_);
    float4 a0=f0[0], a1=f0[1], a2=f0[2], a3=f0[3];
    float4 c0=f1[0], c1=f1[1], c2=f1[2], c3=f1[3];
    float hr[CH_];
    hr[0]=a0.x*w0+c0.x*w; hr[1]=a0.y*w0+c0.y*w; hr[2]=a0.z*w0+c0.z*w; hr[3]=a0.w*w0+c0.w*w;
    hr[4]=a1.x*w0+c1.x*w; hr[5]=a1.y*w0+c1.y*w; hr[6]=a1.z*w0+c1.z*w; hr[7]=a1.w*w0+c1.w*w;
    hr[8]=a2.x*w0+c2.x*w; hr[9]=a2.y*w0+c2.y*w; hr[10]=a2.z*w0+c2.z*w; hr[11]=a2.w*w0+c2.w*w;
    hr[12]=a3.x*w0+c3.x*w; hr[13]=a3.y*w0+c3.y*w; hr[14]=a3.z*w0+c3.z*w; hr[15]=a3.w*w0+c3.w*w;
    #pragma unroll
    for (int o = 0; o < CH_; o++) hr[o] = fmaxf(ssc[o]*hr[o] + ssh[o], 0.f);
    #pragma unroll
    for (int o2 = 0; o2 < CH_; o2++) {
        float acc = sb2[o2];
        #pragma unroll
        for (int o = 0; o < CH_; o++) acc += sW2[o2*16+o] * hr[o];
        out[((size_t)(b*CH_+o2))*L_ + l] = acc;
    }
}

extern "C" void kernel_launch(void* const* d_in, const int* in_sizes, int n_in,
                              void* d_out, int out_size) {
    const float* x     = (const float*)d_in[0];
    const int*   coord = (const int*)  d_in[1];
    const float* Wf    = (const float*)d_in[2];
    const float* bf    = (const float*)d_in[3];
    const float* Wr    = (const float*)d_in[4];
    const float* br    = (const float*)d_in[5];
    const float* W1    = (const float*)d_in[6];
    const float* b1    = (const float*)d_in[7];
    const float* gamma = (const float*)d_in[8];
    const float* beta  = (const float*)d_in[9];
    const float* W2    = (const float*)d_in[10];
    const float* b2    = (const float*)d_in[11];
    float* out = (float*)d_out;

    k_main <<<2048, 128>>>(x, coord, Wr, br, W1, Wf, b1, bf);
    k_stats<<<32,   256>>>();
    k_fin  <<<4800, 256>>>(gamma, beta, W2, b2, out);
}